// round 8
// baseline (speedup 1.0000x reference)
#include <cuda_runtime.h>
#include <cuda_bf16.h>

// IF spiking neuron forward (non-align, T>0):
//   x: [T, B, 1024, 3072] fp32 (flattened T*B), thresh2/dtmem: [1024,3072]
//   mem0 = dtmem*thre; per t: mem += x_t; spike = (mem>=thre)?thre:0; mem -= spike
//
// R8 = R7 minus the __ldcs/__stcs streaming hints.
// Evidence: R1 (no hints) hit 86.6% DRAM; every hinted variant sits 75-83%
// at comparable occupancy/load-batching. The hints were protecting param L2
// residency, but param sharing is achieved by launch-order co-residence
// (batch in LOW 3 bits of blockIdx.x -> the 8 batch-blocks per 256-f param
// range are wave-adjacent and hit L2 immediately), so the hints only tax the
// LTS path. Shape otherwise identical: B_PER_TH=1, all 4 t-loads front-
// batched before the compute recurrence, regs=32, occ~79%.

#define T_STEPS 4
#define B_BATCH 8
#define FEAT_N  (1024u * 3072u)       // 3,145,728 feature elements
#define N4      (FEAT_N / 4u)         // 786,432 float4 per feature map

__global__ __launch_bounds__(256, 6) void if_fwd_kernel(
    const float4* __restrict__ x,
    const float4* __restrict__ thresh,
    const float4* __restrict__ dtm,
    float4* __restrict__ out)
{
    const unsigned bid = blockIdx.x;
    const unsigned b   = bid & 7u;                          // batch index 0..7
    const unsigned f   = (bid >> 3) * 256u + threadIdx.x;   // feature float4 index
    if (f >= N4) return;

    const size_t tstride = (size_t)B_BATCH * N4;
    const float4* __restrict__ xp = x   + (size_t)b * N4 + f;
    float4* __restrict__       op = out + (size_t)b * N4 + f;

    // Front-batch ALL timestep loads (address-independent; only the membrane
    // recurrence is sequential, and that's pure compute).
    const float4 xv0 = xp[0];
    const float4 xv1 = xp[tstride];
    const float4 xv2 = xp[2 * tstride];
    const float4 xv3 = xp[3 * tstride];

    const float4 th = thresh[f];
    const float4 dm = dtm[f];

    float mx = dm.x * th.x;
    float my = dm.y * th.y;
    float mz = dm.z * th.z;
    float mw = dm.w * th.w;

    float4 sp;

    // t = 0
    mx += xv0.x; my += xv0.y; mz += xv0.z; mw += xv0.w;
    sp.x = (mx - th.x >= 0.0f) ? th.x : 0.0f;
    sp.y = (my - th.y >= 0.0f) ? th.y : 0.0f;
    sp.z = (mz - th.z >= 0.0f) ? th.z : 0.0f;
    sp.w = (mw - th.w >= 0.0f) ? th.w : 0.0f;
    mx -= sp.x; my -= sp.y; mz -= sp.z; mw -= sp.w;
    op[0] = sp;

    // t = 1
    mx += xv1.x; my += xv1.y; mz += xv1.z; mw += xv1.w;
    sp.x = (mx - th.x >= 0.0f) ? th.x : 0.0f;
    sp.y = (my - th.y >= 0.0f) ? th.y : 0.0f;
    sp.z = (mz - th.z >= 0.0f) ? th.z : 0.0f;
    sp.w = (mw - th.w >= 0.0f) ? th.w : 0.0f;
    mx -= sp.x; my -= sp.y; mz -= sp.z; mw -= sp.w;
    op[tstride] = sp;

    // t = 2
    mx += xv2.x; my += xv2.y; mz += xv2.z; mw += xv2.w;
    sp.x = (mx - th.x >= 0.0f) ? th.x : 0.0f;
    sp.y = (my - th.y >= 0.0f) ? th.y : 0.0f;
    sp.z = (mz - th.z >= 0.0f) ? th.z : 0.0f;
    sp.w = (mw - th.w >= 0.0f) ? th.w : 0.0f;
    mx -= sp.x; my -= sp.y; mz -= sp.z; mw -= sp.w;
    op[2 * tstride] = sp;

    // t = 3
    mx += xv3.x; my += xv3.y; mz += xv3.z; mw += xv3.w;
    sp.x = (mx - th.x >= 0.0f) ? th.x : 0.0f;
    sp.y = (my - th.y >= 0.0f) ? th.y : 0.0f;
    sp.z = (mz - th.z >= 0.0f) ? th.z : 0.0f;
    sp.w = (mw - th.w >= 0.0f) ? th.w : 0.0f;
    mx -= sp.x; my -= sp.y; mz -= sp.z; mw -= sp.w;
    op[3 * tstride] = sp;
}

extern "C" void kernel_launch(void* const* d_in, const int* in_sizes, int n_in,
                              void* d_out, int out_size)
{
    const float4* x      = (const float4*)d_in[0];
    const float4* thresh = (const float4*)d_in[1];
    const float4* dtm    = (const float4*)d_in[2];
    float4* out          = (float4*)d_out;

    const int threads = 256;
    const int blocks  = (N4 / threads) * B_BATCH;   // 24576 blocks
    if_fwd_kernel<<<blocks, threads>>>(x, thresh, dtm, out);
}